// round 7
// baseline (speedup 1.0000x reference)
#include <cuda_runtime.h>

#define TT 32
#define PP 16
#define NN 65536
#define HH 128
#define NTHREADS 128
#define NBLOCKS 512          // 512 * 128 = 65536 points, 1 per thread

#define OFF_ARG (TT * NN * 3)      // 6291456
#define OFF_TL  (OFF_ARG + NN)     // 6356992

// packed weights + rotation table, produced by prep kernel (static device mem: allowed)
__device__ __align__(16) float g_w1b1[HH * 4];        // [h]: w1x,w1y,w1z,b1
__device__ __align__(16) float g_w2p[HH * 16];        // [h]: 8 pairs (w2[2p][h], w2[2p+1][h])
__device__ __align__(16) float g_R[TT * PP * 12];     // rotation rows + translation

__device__ __forceinline__ unsigned long long packrep(float a) {
    unsigned long long r;
    asm("mov.b64 %0, {%1, %1};" : "=l"(r) : "f"(a));
    return r;
}
__device__ __forceinline__ void fma2(unsigned long long& d, unsigned long long a, unsigned long long b) {
    asm("fma.rn.f32x2 %0, %1, %2, %0;" : "+l"(d) : "l"(a), "l"(b));
}
__device__ __forceinline__ void unpack2(unsigned long long v, float& lo, float& hi) {
    asm("mov.b64 {%0, %1}, %2;" : "=f"(lo), "=f"(hi) : "l"(v));
}

// ---------- prep: pack weights, build R table, write trans_list ----------
__global__ void __launch_bounds__(512) prep_kernel(
    const float* __restrict__ w1, const float* __restrict__ b1,
    const float* __restrict__ w2, const float* __restrict__ p6d,
    const float* __restrict__ pt, float* __restrict__ out)
{
    const int tid = threadIdx.x;

    if (tid < HH) {
        g_w1b1[4 * tid + 0] = w1[3 * tid + 0];
        g_w1b1[4 * tid + 1] = w1[3 * tid + 1];
        g_w1b1[4 * tid + 2] = w1[3 * tid + 2];
        g_w1b1[4 * tid + 3] = b1[tid];
    }
    #pragma unroll
    for (int k = 0; k < 2; k++) {
        int idx = k * 512 + tid;          // 0..1023 pair slots
        int h = idx & (HH - 1);
        int pp = idx >> 7;                // 0..7
        g_w2p[h * 16 + 2 * pp + 0] = w2[(2 * pp) * HH + h];
        g_w2p[h * 16 + 2 * pp + 1] = w2[(2 * pp + 1) * HH + h];
    }
    {
        int e = tid;                      // 0..511 = t*16+p
        float a1x = p6d[e * 6 + 0], a1y = p6d[e * 6 + 1], a1z = p6d[e * 6 + 2];
        float a2x = p6d[e * 6 + 3], a2y = p6d[e * 6 + 4], a2z = p6d[e * 6 + 5];
        float inv = rsqrtf(a1x * a1x + a1y * a1y + a1z * a1z);
        float b1x = a1x * inv, b1y = a1y * inv, b1z = a1z * inv;
        float d = b1x * a2x + b1y * a2y + b1z * a2z;
        float cx = a2x - d * b1x, cy = a2y - d * b1y, cz = a2z - d * b1z;
        float inv2 = rsqrtf(cx * cx + cy * cy + cz * cz);
        float b2x = cx * inv2, b2y = cy * inv2, b2z = cz * inv2;
        float b3x = b1y * b2z - b1z * b2y;
        float b3y = b1z * b2x - b1x * b2z;
        float b3z = b1x * b2y - b1y * b2x;
        float t0 = pt[e * 3 + 0], t1 = pt[e * 3 + 1], t2 = pt[e * 3 + 2];
        float* r = g_R + e * 12;
        r[0] = b1x; r[1] = b1y; r[2] = b1z;
        r[3] = b2x; r[4] = b2y; r[5] = b2z;
        r[6] = b3x; r[7] = b3y; r[8] = b3z;
        r[9] = t0;  r[10] = t1; r[11] = t2;
        float* o = out + OFF_TL + e * 16;
        o[0] = b1x; o[1] = b1y; o[2]  = b1z; o[3]  = t0;
        o[4] = b2x; o[5] = b2y; o[6]  = b2z; o[7]  = t1;
        o[8] = b3x; o[9] = b3y; o[10] = b3z; o[11] = t2;
        o[12] = 0.f; o[13] = 0.f; o[14] = 0.f; o[15] = 1.f;
    }
}

// ---------- main: MLP via broadcast-LDG weights, R via smem ----------
__global__ void __launch_bounds__(NTHREADS) fused_kernel(
    const float* __restrict__ cano, const float* __restrict__ b2,
    const float* __restrict__ gum, float* __restrict__ out)
{
    __shared__ __align__(16) float s_R[TT * PP][12];

    const int tid = threadIdx.x;

    // stage R table: 1536 float4, coalesced
    {
        const float4* src = reinterpret_cast<const float4*>(g_R);
        float4* dst = reinterpret_cast<float4*>(&s_R[0][0]);
        #pragma unroll
        for (int k = 0; k < 12; k++)
            dst[k * NTHREADS + tid] = src[k * NTHREADS + tid];
    }

    const int p = blockIdx.x * NTHREADS + tid;
    const float xx = cano[p * 3], xy = cano[p * 3 + 1], xz = cano[p * 3 + 2];

    // prefetch gumbel (latency hidden under MLP loop)
    const float4* g4 = reinterpret_cast<const float4*>(gum + (size_t)p * PP);
    float4 g0 = g4[0], g1 = g4[1], g2 = g4[2], g3 = g4[3];

    unsigned long long seg[8];
    {
        const unsigned long long* b2p = reinterpret_cast<const unsigned long long*>(b2);
        #pragma unroll
        for (int k = 0; k < 8; k++) seg[k] = b2p[k];
    }

    __syncthreads();

    // MLP: weights via uniform-address (broadcast) global loads — 1 line/LDG
    const float4* w1v = reinterpret_cast<const float4*>(g_w1b1);
    const ulonglong2* w2v = reinterpret_cast<const ulonglong2*>(g_w2p);
    #pragma unroll 4
    for (int h = 0; h < HH; h++) {
        float4 w = w1v[h];
        float hv = fmaxf(fmaf(xx, w.x, fmaf(xy, w.y, fmaf(xz, w.z, w.w))), 0.0f);
        unsigned long long h2 = packrep(hv);
        ulonglong2 q0 = w2v[4 * h + 0];
        ulonglong2 q1 = w2v[4 * h + 1];
        ulonglong2 q2 = w2v[4 * h + 2];
        ulonglong2 q3 = w2v[4 * h + 3];
        fma2(seg[0], h2, q0.x);
        fma2(seg[1], h2, q0.y);
        fma2(seg[2], h2, q1.x);
        fma2(seg[3], h2, q1.y);
        fma2(seg[4], h2, q2.x);
        fma2(seg[5], h2, q2.y);
        fma2(seg[6], h2, q3.x);
        fma2(seg[7], h2, q3.y);
    }

    float s[16];
    #pragma unroll
    for (int k = 0; k < 8; k++)
        unpack2(seg[k], s[2 * k], s[2 * k + 1]);

    // argmax(seg) — first-occurrence semantics
    int ia = 0; float m = s[0];
    #pragma unroll
    for (int q = 1; q < PP; q++)
        if (s[q] > m) { m = s[q]; ia = q; }
    out[OFF_ARG + p] = (float)ia;

    // argmax(seg + gumbel)
    const float gg[16] = { g0.x, g0.y, g0.z, g0.w, g1.x, g1.y, g1.z, g1.w,
                           g2.x, g2.y, g2.z, g2.w, g3.x, g3.y, g3.z, g3.w };
    int sel = 0; float vm = -1e30f;
    #pragma unroll
    for (int q = 0; q < PP; q++) {
        float a = s[q] + gg[q];
        if (a > vm) { vm = a; sel = q; }
    }

    // epilogue: pc_out[t,p,:] = R[t,sel] @ x + t[t,sel]
    #pragma unroll 4
    for (int t = 0; t < TT; t++) {
        const float4* R = reinterpret_cast<const float4*>(s_R[t * PP + sel]);
        float4 r0 = R[0], r1 = R[1], r2 = R[2];
        float o0 = fmaf(xx, r0.x, fmaf(xy, r0.y, fmaf(xz, r0.z, r2.y)));
        float o1 = fmaf(xx, r0.w, fmaf(xy, r1.x, fmaf(xz, r1.y, r2.z)));
        float o2 = fmaf(xx, r1.z, fmaf(xy, r1.w, fmaf(xz, r2.x, r2.w)));
        float* dst = out + (size_t)(t * NN + p) * 3;
        dst[0] = o0;
        dst[1] = o1;
        dst[2] = o2;
    }
}

extern "C" void kernel_launch(void* const* d_in, const int* in_sizes, int n_in,
                              void* d_out, int out_size) {
    (void)in_sizes; (void)n_in; (void)out_size;
    prep_kernel<<<1, 512>>>(
        (const float*)d_in[1],  // w1
        (const float*)d_in[2],  // b1
        (const float*)d_in[3],  // w2
        (const float*)d_in[5],  // proposal_6d
        (const float*)d_in[6],  // proposal_t
        (float*)d_out);
    fused_kernel<<<NBLOCKS, NTHREADS>>>(
        (const float*)d_in[0],  // cano_pc
        (const float*)d_in[4],  // b2
        (const float*)d_in[7],  // gumbel
        (float*)d_out);
}

// round 11
// speedup vs baseline: 1.5215x; 1.5215x over previous
#include <cuda_runtime.h>

#define TT 32
#define PP 16
#define NN 65536
#define HH 128
#define NTHREADS 128
#define NBLOCKS 256   // 256 blocks * 128 threads * 2 points = 65536

#define OFF_ARG (TT * NN * 3)      // 6291456
#define OFF_TL  (OFF_ARG + NN)     // 6356992

// packed by prep kernel (device globals: allowed), then copied into constant bank
__device__ __align__(16) float4 g_wc[HH * 3];    // [3h]=w1xyz+b1, [3h+1]=w2 p0..3, [3h+2]=w2 p4..7
__device__ __align__(16) float4 g_w2s[HH * 2];   // [2h]=w2 p8..11, [2h+1]=w2 p12..15
__device__ __align__(16) float  g_R[TT * PP * 12];

__constant__ __align__(16) float4 c_wc[HH * 3];  // 6 KB in constant bank

__device__ __forceinline__ unsigned long long packrep(float a) {
    unsigned long long r;
    asm("mov.b64 %0, {%1, %1};" : "=l"(r) : "f"(a));
    return r;
}
__device__ __forceinline__ void fma2(unsigned long long& d, unsigned long long a, unsigned long long b) {
    asm("fma.rn.f32x2 %0, %1, %2, %0;" : "+l"(d) : "l"(a), "l"(b));
}
__device__ __forceinline__ void unpack2(unsigned long long v, float& lo, float& hi) {
    asm("mov.b64 {%0, %1}, %2;" : "=f"(lo), "=f"(hi) : "l"(v));
}

// ---------- prep: pack weights, build R table, write trans_list ----------
__global__ void __launch_bounds__(512) prep_kernel(
    const float* __restrict__ w1, const float* __restrict__ b1,
    const float* __restrict__ w2, const float* __restrict__ p6d,
    const float* __restrict__ pt, float* __restrict__ out)
{
    const int tid = threadIdx.x;

    if (tid < HH) {
        int h = tid;
        g_wc[3 * h + 0] = make_float4(w1[3 * h], w1[3 * h + 1], w1[3 * h + 2], b1[h]);
        g_wc[3 * h + 1] = make_float4(w2[0 * HH + h], w2[1 * HH + h], w2[2 * HH + h], w2[3 * HH + h]);
        g_wc[3 * h + 2] = make_float4(w2[4 * HH + h], w2[5 * HH + h], w2[6 * HH + h], w2[7 * HH + h]);
        g_w2s[2 * h + 0] = make_float4(w2[8 * HH + h], w2[9 * HH + h], w2[10 * HH + h], w2[11 * HH + h]);
        g_w2s[2 * h + 1] = make_float4(w2[12 * HH + h], w2[13 * HH + h], w2[14 * HH + h], w2[15 * HH + h]);
    }
    {
        int e = tid;                      // 0..511 = t*16+p
        float a1x = p6d[e * 6 + 0], a1y = p6d[e * 6 + 1], a1z = p6d[e * 6 + 2];
        float a2x = p6d[e * 6 + 3], a2y = p6d[e * 6 + 4], a2z = p6d[e * 6 + 5];
        float inv = rsqrtf(a1x * a1x + a1y * a1y + a1z * a1z);
        float b1x = a1x * inv, b1y = a1y * inv, b1z = a1z * inv;
        float d = b1x * a2x + b1y * a2y + b1z * a2z;
        float cx = a2x - d * b1x, cy = a2y - d * b1y, cz = a2z - d * b1z;
        float inv2 = rsqrtf(cx * cx + cy * cy + cz * cz);
        float b2x = cx * inv2, b2y = cy * inv2, b2z = cz * inv2;
        float b3x = b1y * b2z - b1z * b2y;
        float b3y = b1z * b2x - b1x * b2z;
        float b3z = b1x * b2y - b1y * b2x;
        float t0 = pt[e * 3 + 0], t1 = pt[e * 3 + 1], t2 = pt[e * 3 + 2];
        float* r = g_R + e * 12;
        r[0] = b1x; r[1] = b1y; r[2] = b1z;
        r[3] = b2x; r[4] = b2y; r[5] = b2z;
        r[6] = b3x; r[7] = b3y; r[8] = b3z;
        r[9] = t0;  r[10] = t1; r[11] = t2;
        float* o = out + OFF_TL + e * 16;
        o[0] = b1x; o[1] = b1y; o[2]  = b1z; o[3]  = t0;
        o[4] = b2x; o[5] = b2y; o[6]  = b2z; o[7]  = t1;
        o[8] = b3x; o[9] = b3y; o[10] = b3z; o[11] = t2;
        o[12] = 0.f; o[13] = 0.f; o[14] = 0.f; o[15] = 1.f;
    }
}

// ---------- main: weights via constant port + half smem; R via smem ----------
__global__ void __launch_bounds__(NTHREADS) fused_kernel(
    const float* __restrict__ cano, const float* __restrict__ b2,
    const float* __restrict__ gum, float* __restrict__ out)
{
    __shared__ __align__(16) float s_R[TT * PP][12];   // 24 KB
    __shared__ __align__(16) float4 s_w2[HH * 2];      // 4 KB: w2 p8..15 pairs

    const int tid = threadIdx.x;

    // stage R table (1536 float4) + smem half of w2 (256 float4), coalesced
    {
        const float4* src = reinterpret_cast<const float4*>(g_R);
        float4* dst = reinterpret_cast<float4*>(&s_R[0][0]);
        #pragma unroll
        for (int k = 0; k < 12; k++)
            dst[k * NTHREADS + tid] = src[k * NTHREADS + tid];
        #pragma unroll
        for (int k = 0; k < 2; k++)
            s_w2[k * NTHREADS + tid] = g_w2s[k * NTHREADS + tid];
    }

    const int i = blockIdx.x * NTHREADS + tid;
    const int nA = 2 * i, nB = nA + 1;

    // cano: 24*i byte offset is 8-aligned only -> float2 loads
    const float2* c2 = reinterpret_cast<const float2*>(cano + (size_t)nA * 3);
    float2 ca = c2[0], cb = c2[1], cc = c2[2];
    const float xAx = ca.x, xAy = ca.y, xAz = cb.x;
    const float xBx = cb.y, xBy = cc.x, xBz = cc.y;

    // gumbel: 128*i byte offset, 16-aligned -> float4 ok
    const float4* g4A = reinterpret_cast<const float4*>(gum + (size_t)nA * PP);
    float4 gA0 = g4A[0], gA1 = g4A[1], gA2 = g4A[2], gA3 = g4A[3];
    float4 gB0 = g4A[4], gB1 = g4A[5], gB2 = g4A[6], gB3 = g4A[7];

    unsigned long long segA[8], segB[8];
    {
        const unsigned long long* b2p = reinterpret_cast<const unsigned long long*>(b2);
        #pragma unroll
        for (int k = 0; k < 8; k++) { segA[k] = b2p[k]; segB[k] = b2p[k]; }
    }

    __syncthreads();

    // MLP: w1b1 + p0..7 from constant port, p8..15 from smem
    #pragma unroll 4
    for (int h = 0; h < HH; h++) {
        float4 w = c_wc[3 * h];
        float hA = fmaxf(fmaf(xAx, w.x, fmaf(xAy, w.y, fmaf(xAz, w.z, w.w))), 0.0f);
        float hB = fmaxf(fmaf(xBx, w.x, fmaf(xBy, w.y, fmaf(xBz, w.z, w.w))), 0.0f);
        unsigned long long hA2 = packrep(hA);
        unsigned long long hB2 = packrep(hB);
        ulonglong2 qa = *reinterpret_cast<const ulonglong2*>(&c_wc[3 * h + 1]);
        ulonglong2 qb = *reinterpret_cast<const ulonglong2*>(&c_wc[3 * h + 2]);
        ulonglong2 qc = *reinterpret_cast<const ulonglong2*>(&s_w2[2 * h + 0]);
        ulonglong2 qd = *reinterpret_cast<const ulonglong2*>(&s_w2[2 * h + 1]);
        fma2(segA[0], hA2, qa.x); fma2(segB[0], hB2, qa.x);
        fma2(segA[1], hA2, qa.y); fma2(segB[1], hB2, qa.y);
        fma2(segA[2], hA2, qb.x); fma2(segB[2], hB2, qb.x);
        fma2(segA[3], hA2, qb.y); fma2(segB[3], hB2, qb.y);
        fma2(segA[4], hA2, qc.x); fma2(segB[4], hB2, qc.x);
        fma2(segA[5], hA2, qc.y); fma2(segB[5], hB2, qc.y);
        fma2(segA[6], hA2, qd.x); fma2(segB[6], hB2, qd.x);
        fma2(segA[7], hA2, qd.y); fma2(segB[7], hB2, qd.y);
    }

    float sA[16], sB[16];
    #pragma unroll
    for (int k = 0; k < 8; k++) {
        unpack2(segA[k], sA[2 * k], sA[2 * k + 1]);
        unpack2(segB[k], sB[2 * k], sB[2 * k + 1]);
    }

    // argmax(seg) — first-occurrence semantics (float2 store: 8*i bytes, 8-aligned ok)
    int iaA = 0, iaB = 0;
    float mA = sA[0], mB = sB[0];
    #pragma unroll
    for (int p = 1; p < PP; p++) {
        if (sA[p] > mA) { mA = sA[p]; iaA = p; }
        if (sB[p] > mB) { mB = sB[p]; iaB = p; }
    }
    reinterpret_cast<float2*>(out + OFF_ARG + nA)[0] = make_float2((float)iaA, (float)iaB);

    // selection = argmax(seg + gumbel)
    const float ggA[16] = { gA0.x, gA0.y, gA0.z, gA0.w, gA1.x, gA1.y, gA1.z, gA1.w,
                            gA2.x, gA2.y, gA2.z, gA2.w, gA3.x, gA3.y, gA3.z, gA3.w };
    const float ggB[16] = { gB0.x, gB0.y, gB0.z, gB0.w, gB1.x, gB1.y, gB1.z, gB1.w,
                            gB2.x, gB2.y, gB2.z, gB2.w, gB3.x, gB3.y, gB3.z, gB3.w };
    int selA = 0, selB = 0;
    float vmA = -1e30f, vmB = -1e30f;
    #pragma unroll
    for (int q = 0; q < PP; q++) {
        float a = sA[q] + ggA[q];
        float b = sB[q] + ggB[q];
        if (a > vmA) { vmA = a; selA = q; }
        if (b > vmB) { vmB = b; selB = q; }
    }

    // epilogue: pc_out[t,n,:] = R[t,sel] @ x + t[t,sel]
    // dst byte offset = (t*NN + nA)*12 = ...*24*i -> 8-aligned only: float2 stores
    #pragma unroll 4
    for (int t = 0; t < TT; t++) {
        const float4* RA = reinterpret_cast<const float4*>(s_R[t * PP + selA]);
        float4 a0 = RA[0], a1 = RA[1], a2 = RA[2];
        float oA0 = fmaf(xAx, a0.x, fmaf(xAy, a0.y, fmaf(xAz, a0.z, a2.y)));
        float oA1 = fmaf(xAx, a0.w, fmaf(xAy, a1.x, fmaf(xAz, a1.y, a2.z)));
        float oA2 = fmaf(xAx, a1.z, fmaf(xAy, a1.w, fmaf(xAz, a2.x, a2.w)));
        const float4* RB = reinterpret_cast<const float4*>(s_R[t * PP + selB]);
        float4 c0 = RB[0], c1 = RB[1], c2 = RB[2];
        float oB0 = fmaf(xBx, c0.x, fmaf(xBy, c0.y, fmaf(xBz, c0.z, c2.y)));
        float oB1 = fmaf(xBx, c0.w, fmaf(xBy, c1.x, fmaf(xBz, c1.y, c2.z)));
        float oB2 = fmaf(xBx, c1.z, fmaf(xBy, c1.w, fmaf(xBz, c2.x, c2.w)));
        float2* dst = reinterpret_cast<float2*>(out + (size_t)(t * NN + nA) * 3);
        dst[0] = make_float2(oA0, oA1);
        dst[1] = make_float2(oA2, oB0);
        dst[2] = make_float2(oB1, oB2);
    }
}

extern "C" void kernel_launch(void* const* d_in, const int* in_sizes, int n_in,
                              void* d_out, int out_size) {
    (void)in_sizes; (void)n_in; (void)out_size;
    prep_kernel<<<1, 512>>>(
        (const float*)d_in[1],  // w1
        (const float*)d_in[2],  // b1
        (const float*)d_in[3],  // w2
        (const float*)d_in[5],  // proposal_6d
        (const float*)d_in[6],  // proposal_t
        (float*)d_out);
    void* src = nullptr;
    cudaGetSymbolAddress(&src, g_wc);
    cudaMemcpyToSymbolAsync(c_wc, src, sizeof(float4) * HH * 3, 0,
                            cudaMemcpyDeviceToDevice, 0);
    fused_kernel<<<NBLOCKS, NTHREADS>>>(
        (const float*)d_in[0],  // cano_pc
        (const float*)d_in[4],  // b2
        (const float*)d_in[7],  // gumbel
        (float*)d_out);
}

// round 12
// speedup vs baseline: 2.0345x; 1.3372x over previous
#include <cuda_runtime.h>

#define TT 32
#define PP 16
#define NN 65536
#define HH 128
#define NTHREADS 128
#define NBLOCKS 256   // 256 blocks * 128 threads * 2 points = 65536

#define OFF_ARG (TT * NN * 3)      // 6291456
#define OFF_TL  (OFF_ARG + NN)     // 6356992

__device__ __forceinline__ unsigned long long packrep(float a) {
    unsigned long long r;
    asm("mov.b64 %0, {%1, %1};" : "=l"(r) : "f"(a));
    return r;
}
__device__ __forceinline__ void fma2(unsigned long long& d, unsigned long long a, unsigned long long b) {
    asm("fma.rn.f32x2 %0, %1, %2, %0;" : "+l"(d) : "l"(a), "l"(b));
}
__device__ __forceinline__ void unpack2(unsigned long long v, float& lo, float& hi) {
    asm("mov.b64 {%0, %1}, %2;" : "=f"(lo), "=f"(hi) : "l"(v));
}

__global__ void __launch_bounds__(NTHREADS) fused_kernel(
    const float* __restrict__ cano, const float* __restrict__ w1,
    const float* __restrict__ b1, const float* __restrict__ w2,
    const float* __restrict__ b2, const float* __restrict__ p6d,
    const float* __restrict__ pt, const float* __restrict__ gum,
    float* __restrict__ out)
{
    __shared__ float4 s_w1[HH];                        // w1 row + b1
    __shared__ __align__(16) float4 s_w2[HH][4];       // [h][j] = w2 cols 4j..4j+3 (p-major pairs)
    __shared__ __align__(16) float s_R[TT * PP][12];   // R rows + t

    const int tid = threadIdx.x;

    // ---- stage weights into shared memory ----
    s_w1[tid] = make_float4(w1[3 * tid], w1[3 * tid + 1], w1[3 * tid + 2], b1[tid]);
    #pragma unroll
    for (int k = 0; k < 4; k++)
        s_w2[tid][k] = make_float4(w2[(4 * k + 0) * HH + tid], w2[(4 * k + 1) * HH + tid],
                                   w2[(4 * k + 2) * HH + tid], w2[(4 * k + 3) * HH + tid]);

    // ---- per-block rotation table (redundant across blocks; avoids 2nd launch) ----
    #pragma unroll
    for (int k = 0; k < 4; k++) {
        int e = k * NTHREADS + tid;       // 0..511 = t*16+p
        float a1x = p6d[e * 6 + 0], a1y = p6d[e * 6 + 1], a1z = p6d[e * 6 + 2];
        float a2x = p6d[e * 6 + 3], a2y = p6d[e * 6 + 4], a2z = p6d[e * 6 + 5];
        float inv = rsqrtf(a1x * a1x + a1y * a1y + a1z * a1z);
        float b1x = a1x * inv, b1y = a1y * inv, b1z = a1z * inv;
        float d = b1x * a2x + b1y * a2y + b1z * a2z;
        float cx = a2x - d * b1x, cy = a2y - d * b1y, cz = a2z - d * b1z;
        float inv2 = rsqrtf(cx * cx + cy * cy + cz * cz);
        float b2x = cx * inv2, b2y = cy * inv2, b2z = cz * inv2;
        float b3x = b1y * b2z - b1z * b2y;
        float b3y = b1z * b2x - b1x * b2z;
        float b3z = b1x * b2y - b1y * b2x;
        float t0 = pt[e * 3 + 0], t1 = pt[e * 3 + 1], t2 = pt[e * 3 + 2];
        float* r = s_R[e];
        r[0] = b1x; r[1] = b1y; r[2] = b1z;
        r[3] = b2x; r[4] = b2y; r[5] = b2z;
        r[6] = b3x; r[7] = b3y; r[8] = b3z;
        r[9] = t0;  r[10] = t1; r[11] = t2;
        if (blockIdx.x == 0) {
            float* o = out + OFF_TL + e * 16;
            o[0] = b1x; o[1] = b1y; o[2]  = b1z; o[3]  = t0;
            o[4] = b2x; o[5] = b2y; o[6]  = b2z; o[7]  = t1;
            o[8] = b3x; o[9] = b3y; o[10] = b3z; o[11] = t2;
            o[12] = 0.f; o[13] = 0.f; o[14] = 0.f; o[15] = 1.f;
        }
    }

    const int i = blockIdx.x * NTHREADS + tid;
    const int nA = 2 * i;

    // cano: 24*i bytes -> 8-aligned only: float2 loads
    const float2* c2 = reinterpret_cast<const float2*>(cano + (size_t)nA * 3);
    float2 ca = c2[0], cb = c2[1], cc = c2[2];
    const float xAx = ca.x, xAy = ca.y, xAz = cb.x;
    const float xBx = cb.y, xBy = cc.x, xBz = cc.y;

    unsigned long long segA[8], segB[8];
    {
        const unsigned long long* b2p = reinterpret_cast<const unsigned long long*>(b2);
        #pragma unroll
        for (int k = 0; k < 8; k++) { segA[k] = b2p[k]; segB[k] = b2p[k]; }
    }

    __syncthreads();

    // ---- MLP with explicit 1-deep software pipeline on the weight stream ----
    float4 w_c  = s_w1[0];
    float4 qa_c = s_w2[0][0], qb_c = s_w2[0][1], qc_c = s_w2[0][2], qd_c = s_w2[0][3];

    #pragma unroll 4
    for (int h = 0; h < HH; h++) {
        // prefetch next iteration's weights (wraps on last iter; harmless)
        const int hn = (h + 1) & (HH - 1);
        float4 w_n  = s_w1[hn];
        float4 qa_n = s_w2[hn][0];
        float4 qb_n = s_w2[hn][1];
        float4 qc_n = s_w2[hn][2];
        float4 qd_n = s_w2[hn][3];

        float hA = fmaxf(fmaf(xAx, w_c.x, fmaf(xAy, w_c.y, fmaf(xAz, w_c.z, w_c.w))), 0.0f);
        float hB = fmaxf(fmaf(xBx, w_c.x, fmaf(xBy, w_c.y, fmaf(xBz, w_c.z, w_c.w))), 0.0f);
        unsigned long long hA2 = packrep(hA);
        unsigned long long hB2 = packrep(hB);
        ulonglong2 ua = *reinterpret_cast<ulonglong2*>(&qa_c);
        ulonglong2 ub = *reinterpret_cast<ulonglong2*>(&qb_c);
        ulonglong2 uc = *reinterpret_cast<ulonglong2*>(&qc_c);
        ulonglong2 ud = *reinterpret_cast<ulonglong2*>(&qd_c);
        fma2(segA[0], hA2, ua.x); fma2(segB[0], hB2, ua.x);
        fma2(segA[1], hA2, ua.y); fma2(segB[1], hB2, ua.y);
        fma2(segA[2], hA2, ub.x); fma2(segB[2], hB2, ub.x);
        fma2(segA[3], hA2, ub.y); fma2(segB[3], hB2, ub.y);
        fma2(segA[4], hA2, uc.x); fma2(segB[4], hB2, uc.x);
        fma2(segA[5], hA2, uc.y); fma2(segB[5], hB2, uc.y);
        fma2(segA[6], hA2, ud.x); fma2(segB[6], hB2, ud.x);
        fma2(segA[7], hA2, ud.y); fma2(segB[7], hB2, ud.y);

        w_c = w_n; qa_c = qa_n; qb_c = qb_n; qc_c = qc_n; qd_c = qd_n;
    }

    // gumbel loads issued here; latency overlapped with unpack/argmax below
    const float4* g4 = reinterpret_cast<const float4*>(gum + (size_t)nA * PP);
    float4 gA0 = g4[0], gA1 = g4[1], gA2 = g4[2], gA3 = g4[3];
    float4 gB0 = g4[4], gB1 = g4[5], gB2 = g4[6], gB3 = g4[7];

    float sA[16], sB[16];
    #pragma unroll
    for (int k = 0; k < 8; k++) {
        unpack2(segA[k], sA[2 * k], sA[2 * k + 1]);
        unpack2(segB[k], sB[2 * k], sB[2 * k + 1]);
    }

    // argmax(seg) — first-occurrence semantics
    int iaA = 0, iaB = 0;
    float mA = sA[0], mB = sB[0];
    #pragma unroll
    for (int p = 1; p < PP; p++) {
        if (sA[p] > mA) { mA = sA[p]; iaA = p; }
        if (sB[p] > mB) { mB = sB[p]; iaB = p; }
    }
    reinterpret_cast<float2*>(out + OFF_ARG + nA)[0] = make_float2((float)iaA, (float)iaB);

    // selection = argmax(seg + gumbel)
    const float ggA[16] = { gA0.x, gA0.y, gA0.z, gA0.w, gA1.x, gA1.y, gA1.z, gA1.w,
                            gA2.x, gA2.y, gA2.z, gA2.w, gA3.x, gA3.y, gA3.z, gA3.w };
    const float ggB[16] = { gB0.x, gB0.y, gB0.z, gB0.w, gB1.x, gB1.y, gB1.z, gB1.w,
                            gB2.x, gB2.y, gB2.z, gB2.w, gB3.x, gB3.y, gB3.z, gB3.w };
    int selA = 0, selB = 0;
    float vmA = -1e30f, vmB = -1e30f;
    #pragma unroll
    for (int q = 0; q < PP; q++) {
        float a = sA[q] + ggA[q];
        float b = sB[q] + ggB[q];
        if (a > vmA) { vmA = a; selA = q; }
        if (b > vmB) { vmB = b; selB = q; }
    }

    // epilogue: pc_out[t,n,:] = R[t,sel] @ x + t[t,sel]  (float2 stores: 8-aligned)
    #pragma unroll 4
    for (int t = 0; t < TT; t++) {
        const float4* RA = reinterpret_cast<const float4*>(s_R[t * PP + selA]);
        float4 a0 = RA[0], a1 = RA[1], a2 = RA[2];
        float oA0 = fmaf(xAx, a0.x, fmaf(xAy, a0.y, fmaf(xAz, a0.z, a2.y)));
        float oA1 = fmaf(xAx, a0.w, fmaf(xAy, a1.x, fmaf(xAz, a1.y, a2.z)));
        float oA2 = fmaf(xAx, a1.z, fmaf(xAy, a1.w, fmaf(xAz, a2.x, a2.w)));
        const float4* RB = reinterpret_cast<const float4*>(s_R[t * PP + selB]);
        float4 c0 = RB[0], c1 = RB[1], c2 = RB[2];
        float oB0 = fmaf(xBx, c0.x, fmaf(xBy, c0.y, fmaf(xBz, c0.z, c2.y)));
        float oB1 = fmaf(xBx, c0.w, fmaf(xBy, c1.x, fmaf(xBz, c1.y, c2.z)));
        float oB2 = fmaf(xBx, c1.z, fmaf(xBy, c1.w, fmaf(xBz, c2.x, c2.w)));
        float2* dst = reinterpret_cast<float2*>(out + (size_t)(t * NN + nA) * 3);
        dst[0] = make_float2(oA0, oA1);
        dst[1] = make_float2(oA2, oB0);
        dst[2] = make_float2(oB1, oB2);
    }
}

extern "C" void kernel_launch(void* const* d_in, const int* in_sizes, int n_in,
                              void* d_out, int out_size) {
    (void)in_sizes; (void)n_in; (void)out_size;
    fused_kernel<<<NBLOCKS, NTHREADS>>>(
        (const float*)d_in[0],  // cano_pc
        (const float*)d_in[1],  // w1
        (const float*)d_in[2],  // b1
        (const float*)d_in[3],  // w2
        (const float*)d_in[4],  // b2
        (const float*)d_in[5],  // proposal_6d
        (const float*)d_in[6],  // proposal_t
        (const float*)d_in[7],  // gumbel
        (float*)d_out);
}